// round 10
// baseline (speedup 1.0000x reference)
#include <cuda_runtime.h>
#include <cuda_fp16.h>

#define NN 50000
#define NE 800000
#define NG 256
#define NF 128
#define SCAN_BLK 1024
#define SCAN_NBLK 49   // 49*1024 = 50176 >= NN+1
#define NHALF 25088    // node split point (divisible by 8)

typedef unsigned long long u64;

// ---------------- device scratch (no allocation allowed) ----------------
__device__ __align__(16) __half d_hT[NN * NF];     // dinv-scaled GEMM out
__device__ __align__(16) __half d_hX[NN * NF];     // agg out
__device__ __align__(16) __half d_Wh[3 * NF * NF];
__device__ float  d_dinv[NN];
__device__ int    d_cnt[NN];
__device__ int    d_off[NN + 1];
__device__ int    d_cursor[NN];
__device__ int    d_csrs[NE];        // src only (weights factored out)
__device__ u64    d_agg[64];
__device__ int    d_is64;
__device__ int    d_gstart[NG + 1];
__device__ float  d_mlpo[NG * 64];

__device__ __forceinline__ uint2 pack4h(float4 v) {
    __half2 a = __floats2half2_rn(v.x, v.y);
    __half2 b = __floats2half2_rn(v.z, v.w);
    uint2 r;
    r.x = *(unsigned*)&a;
    r.y = *(unsigned*)&b;
    return r;
}
__device__ __forceinline__ float4 unpack4h(uint2 u) {
    __half2 a = *(__half2*)&u.x;
    __half2 b = *(__half2*)&u.y;
    float2 f0 = __half22float2(a);
    float2 f1 = __half22float2(b);
    return make_float4(f0.x, f0.y, f1.x, f1.y);
}

__device__ __forceinline__ int ldidx(const void* p, long long i) {
    if (d_is64) return (int)((const long long*)p)[i];
    return ((const int*)p)[i];
}

// ---------------- prep ----------------
__global__ void k_init(const void* edge) {
    int i = blockIdx.x * blockDim.x + threadIdx.x;
    if (i == 0) {
        const int* p = (const int*)edge;
        int any = 0;
        for (int j = 0; j < 64; j++) any |= p[2 * j + 1];
        d_is64 = (any == 0) ? 1 : 0;
    }
    if (i < NN) d_cnt[i] = 0;
    if (i < 64) d_agg[i] = 0ull;
}

__global__ void k_hist(const void* edge) {
    int e = blockIdx.x * blockDim.x + threadIdx.x;
    if (e >= NE) return;
    int c = ldidx(edge, (long long)NE + e);
    atomicAdd(&d_cnt[c], 1);
}

// single-pass scan (aggregate lookback) + dinv + cursor
__global__ void k_scan() {
    __shared__ int sm[2][SCAN_BLK];
    __shared__ int pb[64];
    int t = threadIdx.x;
    int bid = blockIdx.x;
    int idx = bid * SCAN_BLK + t;
    int v = (idx < NN) ? d_cnt[idx] : 0;
    sm[0][t] = v;
    __syncthreads();
    int cur = 0;
    for (int d = 1; d < SCAN_BLK; d <<= 1) {
        int add = (t >= d) ? sm[cur][t - d] : 0;
        sm[cur ^ 1][t] = sm[cur][t] + add;
        cur ^= 1;
        __syncthreads();
    }
    int incl = sm[cur][t];
    if (t == SCAN_BLK - 1)
        atomicExch(&d_agg[bid], (1ull << 32) | (unsigned)incl);
    if (t < 64) {
        int val = 0;
        if (t < bid) {
            u64 w;
            do { w = atomicAdd(&d_agg[t], 0ull); } while ((w >> 32) == 0ull);
            val = (int)(unsigned)w;
        }
        pb[t] = val;
    }
    __syncthreads();
    if (t < 32) pb[t] += pb[t + 32];
    __syncthreads();
    if (t < 16) pb[t] += pb[t + 16];
    __syncthreads();
    if (t < 8) pb[t] += pb[t + 8];
    __syncthreads();
    if (t < 4) pb[t] += pb[t + 4];
    __syncthreads();
    int base = pb[0] + pb[1] + pb[2] + pb[3];
    int excl = base + incl - v;
    if (idx <= NN) d_off[idx] = excl;
    if (idx < NN) {
        d_dinv[idx] = rsqrtf((float)v + 1.0f);
        d_cursor[idx] = excl;
    }
}

// CSR fill: src index only, 1 edge/thread (max outstanding atomics)
__global__ void k_fill(const void* edge) {
    int e = blockIdx.x * blockDim.x + threadIdx.x;
    if (e >= NE) return;
    int r = ldidx(edge, e);
    int c = ldidx(edge, (long long)NE + e);
    int p = atomicAdd(&d_cursor[c], 1);
    d_csrs[p] = r;
}

__global__ void k_wconv(const float* __restrict__ W) {
    int i = blockIdx.x * blockDim.x + threadIdx.x;
    if (i < 3 * NF * NF) d_Wh[i] = __float2half(W[i]);
}

__global__ void k_bounds(const void* batch) {
    int i = blockIdx.x * blockDim.x + threadIdx.x;
    if (i >= NN) return;
    int b = ldidx(batch, i);
    int prev = (i == 0) ? -1 : ldidx(batch, i - 1);
    for (int g = prev + 1; g <= b; g++) d_gstart[g] = i;
    if (i == NN - 1) {
        for (int g = b + 1; g <= NG; g++) d_gstart[g] = NN;
    }
}

#define SM_STRIDE 136   // halves; conflict-free mma fragment loads

// ---------------- HMMA core; epilogue scales row n by dinv[n] ----------------
__device__ __forceinline__ void mma_phase(const __half* Asm, const __half* Bsm,
                                          __half* C, int row0, int nrows, int tid)
{
    int lane = tid & 31, wid = tid >> 5;
    int wm = (wid & 3) * 32;
    int wn = (wid >> 2) * 64;
    int r = lane >> 2;
    int c2 = (lane & 3) * 2;

    float acc[2][8][4];
#pragma unroll
    for (int mt = 0; mt < 2; mt++)
#pragma unroll
        for (int nt = 0; nt < 8; nt++)
#pragma unroll
            for (int q = 0; q < 4; q++) acc[mt][nt][q] = 0.f;

#pragma unroll
    for (int ks = 0; ks < 8; ks++) {
        int kb = ks * 16;
        unsigned af[2][4];
#pragma unroll
        for (int mt = 0; mt < 2; mt++) {
            int rowb = wm + mt * 16;
            af[mt][0] = *(unsigned*)&Asm[(rowb + r) * SM_STRIDE + kb + c2];
            af[mt][1] = *(unsigned*)&Asm[(rowb + r + 8) * SM_STRIDE + kb + c2];
            af[mt][2] = *(unsigned*)&Asm[(rowb + r) * SM_STRIDE + kb + c2 + 8];
            af[mt][3] = *(unsigned*)&Asm[(rowb + r + 8) * SM_STRIDE + kb + c2 + 8];
        }
        unsigned bf[8][2];
#pragma unroll
        for (int nt = 0; nt < 8; nt++) {
            int n = wn + nt * 8 + r;
            bf[nt][0] = *(unsigned*)&Bsm[n * SM_STRIDE + kb + c2];
            bf[nt][1] = *(unsigned*)&Bsm[n * SM_STRIDE + kb + c2 + 8];
        }
#pragma unroll
        for (int mt = 0; mt < 2; mt++)
#pragma unroll
            for (int nt = 0; nt < 8; nt++) {
                asm volatile(
                    "mma.sync.aligned.m16n8k16.row.col.f32.f16.f16.f32 "
                    "{%0,%1,%2,%3}, {%4,%5,%6,%7}, {%8,%9}, {%0,%1,%2,%3};"
                    : "+f"(acc[mt][nt][0]), "+f"(acc[mt][nt][1]),
                      "+f"(acc[mt][nt][2]), "+f"(acc[mt][nt][3])
                    : "r"(af[mt][0]), "r"(af[mt][1]), "r"(af[mt][2]), "r"(af[mt][3]),
                      "r"(bf[nt][0]), "r"(bf[nt][1]));
            }
    }

#pragma unroll
    for (int mt = 0; mt < 2; mt++) {
        int gr0 = row0 + wm + mt * 16 + r;
        int gr1 = gr0 + 8;
        float dv0 = (gr0 < nrows) ? d_dinv[gr0] : 0.f;
        float dv1 = (gr1 < nrows) ? d_dinv[gr1] : 0.f;
#pragma unroll
        for (int nt = 0; nt < 8; nt++) {
            int gc = wn + nt * 8 + c2;
            __half2 h0 = __floats2half2_rn(dv0 * acc[mt][nt][0], dv0 * acc[mt][nt][1]);
            __half2 h1 = __floats2half2_rn(dv1 * acc[mt][nt][2], dv1 * acc[mt][nt][3]);
            if (gr0 < nrows) *(__half2*)(C + (size_t)gr0 * 128 + gc) = h0;
            if (gr1 < nrows) *(__half2*)(C + (size_t)gr1 * 128 + gc) = h1;
        }
    }
}

// GEMM over rows [rowBase + blk*128, ...): A fp32 (layer 1) or fp16; C dinv-scaled fp16
__global__ __launch_bounds__(256) void k_gemmT(
    const void* __restrict__ Ap, int a_fp32,
    const __half* __restrict__ Wh,
    __half* __restrict__ C, int rowBase, int nrows)
{
    extern __shared__ __half smh[];
    __half* Asm = smh;
    __half* Bsm = smh + 128 * SM_STRIDE;
    int tid = threadIdx.x;
    int row0 = rowBase + blockIdx.x * 128;

    if (a_fp32) {
        const float* Af = (const float*)Ap;
#pragma unroll
        for (int i = 0; i < 16; i++) {
            int idx = tid + i * 256;
            int row = idx >> 5;
            int c4 = (idx & 31) << 2;
            float4 v = make_float4(0.f, 0.f, 0.f, 0.f);
            if (row0 + row < nrows)
                v = *(const float4*)(Af + (size_t)(row0 + row) * 128 + c4);
            *(uint2*)&Asm[row * SM_STRIDE + c4] = pack4h(v);
        }
    } else {
        const uint4* Ah = (const uint4*)Ap;
#pragma unroll
        for (int i = 0; i < 8; i++) {
            int idx = tid + i * 256;
            int row = idx >> 4;
            int c8 = (idx & 15) << 3;
            uint4 v = make_uint4(0u, 0u, 0u, 0u);
            if (row0 + row < nrows)
                v = Ah[(size_t)(row0 + row) * 16 + (idx & 15)];
            *(uint4*)&Asm[row * SM_STRIDE + c8] = v;
        }
    }
    {
        const uint4* Wv = (const uint4*)Wh;
#pragma unroll
        for (int i = 0; i < 8; i++) {
            int idx = tid + i * 256;
            int row = idx >> 4;
            int c8 = (idx & 15) << 3;
            *(uint4*)&Bsm[row * SM_STRIDE + c8] = Wv[idx];
        }
    }
    __syncthreads();
    mma_phase(Asm, Bsm, C, row0, nrows, tid);
}

// ---------------- agg over node range [nodeBase, nodeEnd) ----------------
__global__ __launch_bounds__(256) void k_agg(const __half* __restrict__ ht,
                                             const float* __restrict__ bias,
                                             __half* __restrict__ out,
                                             int nodeBase, int nodeEnd)
{
    int node = nodeBase + (int)((blockIdx.x * (unsigned)blockDim.x + threadIdx.x) >> 5);
    if (node >= nodeEnd) return;
    int lane = threadIdx.x & 31;
    const uint2* base = (const uint2*)ht;

    float4 a0 = unpack4h(__ldg(base + (size_t)node * 32 + lane));  // self term
    float4 a1 = make_float4(0.f, 0.f, 0.f, 0.f);
    float4 a2 = a1, a3 = a1;

    int p = d_off[node], e = d_off[node + 1];
    for (; p + 8 <= e; p += 8) {
        int ss[8];
        uint2 vv[8];
#pragma unroll
        for (int q = 0; q < 8; q++) ss[q] = __ldg(&d_csrs[p + q]);
#pragma unroll
        for (int q = 0; q < 8; q++) vv[q] = __ldg(base + (size_t)ss[q] * 32 + lane);
#pragma unroll
        for (int q = 0; q < 8; q++) {
            float4 v = unpack4h(vv[q]);
            float4* a = (q & 3) == 0 ? &a0 : (q & 3) == 1 ? &a1 : (q & 3) == 2 ? &a2 : &a3;
            a->x += v.x; a->y += v.y; a->z += v.z; a->w += v.w;
        }
    }
    for (; p < e; p++) {
        int s = __ldg(&d_csrs[p]);
        float4 v = unpack4h(__ldg(base + (size_t)s * 32 + lane));
        a0.x += v.x; a0.y += v.y; a0.z += v.z; a0.w += v.w;
    }
    float dv = d_dinv[node];
    float4 b4 = __ldg((const float4*)bias + lane);
    float4 rv;
    rv.x = fmaxf(fmaf(dv, a0.x + a1.x + a2.x + a3.x, b4.x), 0.f);
    rv.y = fmaxf(fmaf(dv, a0.y + a1.y + a2.y + a3.y, b4.y), 0.f);
    rv.z = fmaxf(fmaf(dv, a0.z + a1.z + a2.z + a3.z, b4.z), 0.f);
    rv.w = fmaxf(fmaf(dv, a0.w + a1.w + a2.w + a3.w, b4.w), 0.f);
    *(uint2*)(out + (size_t)node * 128 + lane * 4) = pack4h(rv);
}

// ---------------- small dense helpers ----------------
__device__ __forceinline__ float dotN(const float* __restrict__ a,
                                      const float* __restrict__ w, int n) {
    float s0 = 0.f, s1 = 0.f, s2 = 0.f, s3 = 0.f;
    for (int k = 0; k < n; k += 4) {
        float4 wv = __ldg((const float4*)(w + k));
        s0 = fmaf(a[k + 0], wv.x, s0);
        s1 = fmaf(a[k + 1], wv.y, s1);
        s2 = fmaf(a[k + 2], wv.z, s2);
        s3 = fmaf(a[k + 3], wv.w, s3);
    }
    return (s0 + s1) + (s2 + s3);
}

__global__ __launch_bounds__(256) void k_mlp(
    const float* __restrict__ mol,
    const float* __restrict__ mW, const float* __restrict__ mB,
    const float* __restrict__ moW, const float* __restrict__ moB)
{
    __shared__ float a[256], b[256];
    int g = blockIdx.x, t = threadIdx.x;
    a[t] = mol[g * 256 + t];
    __syncthreads();
    b[t] = fmaxf(dotN(a, mW + t * 256, 256) + mB[t], 0.f);
    __syncthreads();
    a[t] = fmaxf(dotN(b, mW + 65536 + t * 256, 256) + mB[256 + t], 0.f);
    __syncthreads();
    if (t < 64) d_mlpo[g * 64 + t] = fmaxf(dotN(a, moW + t * 256, 256) + moB[t], 0.f);
}

__global__ __launch_bounds__(256) void k_heads2(
    const __half* __restrict__ hnode,
    const float* __restrict__ goW, const float* __restrict__ goB,
    const float* __restrict__ p1W, const float* __restrict__ p1B,
    const float* __restrict__ p2W, const float* __restrict__ p2B,
    const float* __restrict__ oW, const float* __restrict__ oB,
    float* __restrict__ out)
{
    __shared__ float cat[192], pooled[128], red[256], b[256], a[256];
    int g = blockIdx.x, t = threadIdx.x;

    int s = d_gstart[g], e = d_gstart[g + 1];
    int f = t & 127, half = t >> 7;
    float c0 = 0.f, c1 = 0.f, c2 = 0.f, c3 = 0.f;
    int n = s + half;
    for (; n + 6 < e; n += 8) {
        c0 += __half2float(hnode[(size_t)n * 128 + f]);
        c1 += __half2float(hnode[(size_t)(n + 2) * 128 + f]);
        c2 += __half2float(hnode[(size_t)(n + 4) * 128 + f]);
        c3 += __half2float(hnode[(size_t)(n + 6) * 128 + f]);
    }
    for (; n < e; n += 2)
        c0 += __half2float(hnode[(size_t)n * 128 + f]);
    red[t] = (c0 + c1) + (c2 + c3);
    if (t < 64) cat[128 + t] = d_mlpo[g * 64 + t];
    __syncthreads();
    if (t < 128) pooled[t] = (red[t] + red[t + 128]) / (float)max(e - s, 1);
    __syncthreads();
    if (t < 128) cat[t] = dotN(pooled, goW + t * 128, 128) + goB[t];
    __syncthreads();

    b[t] = fmaxf(dotN(cat, p1W + t * 192, 192) + p1B[t], 0.f);
    __syncthreads();
    a[t] = fmaxf(dotN(b, p2W + t * 256, 256) + p2B[t], 0.f);
    __syncthreads();
    red[t] = a[t] * oW[t];
    __syncthreads();
    for (int d = 128; d > 0; d >>= 1) {
        if (t < d) red[t] += red[t + d];
        __syncthreads();
    }
    if (t == 0) out[g] = red[0] + oB[0];
}

// ---------------- host ----------------
#define GEMM_SMEM (2 * 128 * SM_STRIDE * (int)sizeof(__half))

struct HxCtx {
    cudaStream_t s1, s2;
    cudaEvent_t ev0, ev1, ev2, ev3, ev4;
    cudaEvent_t eA0, eA1, eG1, eB0, eB1, eG2;
    HxCtx() {
        cudaStreamCreateWithFlags(&s1, cudaStreamNonBlocking);
        cudaStreamCreateWithFlags(&s2, cudaStreamNonBlocking);
        cudaEvent_t* evs[11] = {&ev0, &ev1, &ev2, &ev3, &ev4,
                                &eA0, &eA1, &eG1, &eB0, &eB1, &eG2};
        for (int i = 0; i < 11; i++)
            cudaEventCreateWithFlags(evs[i], cudaEventDisableTiming);
        cudaFuncSetAttribute(k_gemmT, cudaFuncAttributeMaxDynamicSharedMemorySize, GEMM_SMEM);
    }
};

extern "C" void kernel_launch(void* const* d_in, const int* in_sizes, int n_in,
                              void* d_out, int out_size)
{
    static HxCtx ctx;

    const float* x    = (const float*)d_in[0];
    const void*  ei   = d_in[1];
    const void*  bi   = d_in[2];
    const float* mol  = (const float*)d_in[3];
    const float* gcnW = (const float*)d_in[4];
    const float* gcnB = (const float*)d_in[5];
    const float* goW  = (const float*)d_in[6];
    const float* goB  = (const float*)d_in[7];
    const float* mW   = (const float*)d_in[8];
    const float* mB   = (const float*)d_in[9];
    const float* moW  = (const float*)d_in[10];
    const float* moB  = (const float*)d_in[11];
    const float* p1W  = (const float*)d_in[12];
    const float* p1B  = (const float*)d_in[13];
    const float* p2W  = (const float*)d_in[14];
    const float* p2B  = (const float*)d_in[15];
    const float* oW   = (const float*)d_in[16];
    const float* oB   = (const float*)d_in[17];
    float* out = (float*)d_out;

    void *pT, *pX, *pW;
    cudaGetSymbolAddress(&pT, d_hT);
    cudaGetSymbolAddress(&pX, d_hX);
    cudaGetSymbolAddress(&pW, d_Wh);
    __half* hT = (__half*)pT;
    __half* hX = (__half*)pX;
    __half* Wh = (__half*)pW;

    const int nthr = 256;
    int gN = (NN + nthr - 1) / nthr;
    int gE = (NE + nthr - 1) / nthr;
    // grids
    int gGemmA = NHALF / 128;                        // 196 (rows [0, NHALF))
    int gGemmB = (NN - NHALF + 127) / 128;           // 195 (rows [NHALF, NN))
    int gAggA = NHALF / 8;                           // 3136 blocks (8 nodes/block)
    int gAggB = (NN - NHALF + 7) / 8;                // 3114
    int gAggFull = (NN * 32 + nthr - 1) / nthr;
    int gGemmFull = (NN + 127) / 128;

    cudaStream_t L = 0;

    // init (+is64 detect, scan flag reset)
    k_init<<<gN, nthr, 0, L>>>(ei);
    cudaEventRecord(ctx.ev0, L);
    cudaStreamWaitEvent(ctx.s1, ctx.ev0, 0);
    cudaStreamWaitEvent(ctx.s2, ctx.ev0, 0);

    // s1: CSR prep (scalar hist/fill — max thread-level MLP)
    k_hist<<<gE, nthr, 0, ctx.s1>>>(ei);
    k_scan<<<SCAN_NBLK, SCAN_BLK, 0, ctx.s1>>>();
    cudaEventRecord(ctx.ev4, ctx.s1);            // dinv ready
    k_fill<<<gE, nthr, 0, ctx.s1>>>(ei);
    cudaEventRecord(ctx.ev1, ctx.s1);            // CSR ready

    // s2: wconv, bounds, mlp
    k_wconv<<<(3 * NF * NF + 255) / 256, 256, 0, ctx.s2>>>(gcnW);
    cudaEventRecord(ctx.ev3, ctx.s2);
    k_bounds<<<gN, nthr, 0, ctx.s2>>>(bi);
    k_mlp<<<NG, nthr, 0, ctx.s2>>>(mol, mW, mB, moW, moB);
    cudaEventRecord(ctx.ev2, ctx.s2);

    // L: GEMM1 (full; overlapped with fill on s1)
    cudaStreamWaitEvent(L, ctx.ev3, 0);
    cudaStreamWaitEvent(L, ctx.ev4, 0);
    k_gemmT<<<gGemmFull, 256, GEMM_SMEM, L>>>(x, 1, Wh, hT, 0, NN);
    cudaStreamWaitEvent(L, ctx.ev1, 0);

    // ---- layer 1 agg + layer 2 gemm, half-split pipeline ----
    k_agg<<<gAggA, 256, 0, L>>>(hT, gcnB, hX, 0, NHALF);
    cudaEventRecord(ctx.eA0, L);
    k_agg<<<gAggB, 256, 0, L>>>(hT, gcnB, hX, NHALF, NN);
    cudaEventRecord(ctx.eA1, L);
    cudaStreamWaitEvent(ctx.s1, ctx.eA0, 0);
    k_gemmT<<<gGemmA, 256, GEMM_SMEM, ctx.s1>>>(hX, 0, Wh + NF * NF, hT, 0, NN);
    cudaStreamWaitEvent(ctx.s1, ctx.eA1, 0);
    k_gemmT<<<gGemmB, 256, GEMM_SMEM, ctx.s1>>>(hX, 0, Wh + NF * NF, hT, NHALF, NN);
    cudaEventRecord(ctx.eG1, ctx.s1);

    // ---- layer 2 agg + layer 3 gemm, half-split pipeline ----
    cudaStreamWaitEvent(L, ctx.eG1, 0);
    k_agg<<<gAggA, 256, 0, L>>>(hT, gcnB + 128, hX, 0, NHALF);
    cudaEventRecord(ctx.eB0, L);
    k_agg<<<gAggB, 256, 0, L>>>(hT, gcnB + 128, hX, NHALF, NN);
    cudaEventRecord(ctx.eB1, L);
    cudaStreamWaitEvent(ctx.s1, ctx.eB0, 0);
    k_gemmT<<<gGemmA, 256, GEMM_SMEM, ctx.s1>>>(hX, 0, Wh + 2 * NF * NF, hT, 0, NN);
    cudaStreamWaitEvent(ctx.s1, ctx.eB1, 0);
    k_gemmT<<<gGemmB, 256, GEMM_SMEM, ctx.s1>>>(hX, 0, Wh + 2 * NF * NF, hT, NHALF, NN);
    cudaEventRecord(ctx.eG2, ctx.s1);

    // ---- layer 3 agg (full) + heads ----
    cudaStreamWaitEvent(L, ctx.eG2, 0);
    k_agg<<<gAggFull, 256, 0, L>>>(hT, gcnB + 256, hX, 0, NN);
    cudaStreamWaitEvent(L, ctx.ev2, 0);
    k_heads2<<<NG, 256, 0, L>>>(hX, goW, goB, p1W, p1B, p2W, p2B, oW, oB, out);
}

// round 11
// speedup vs baseline: 1.0482x; 1.0482x over previous
#include <cuda_runtime.h>
#include <cuda_fp16.h>

#define NN 50000
#define NE 800000
#define NG 256
#define NF 128
#define SCAN_BLK 1024
#define SCAN_NBLK 49   // 49*1024 = 50176 >= NN+1

typedef unsigned long long u64;

// ---------------- device scratch (no allocation allowed) ----------------
__device__ __align__(16) __half d_hT[NN * NF];     // dinv-scaled GEMM out
__device__ __align__(16) __half d_hX[NN * NF];     // agg out
__device__ __align__(16) __half d_Wh[3 * NF * NF];
__device__ float  d_dinv[NN];
__device__ __align__(16) int d_cnt[NN];
__device__ int    d_off[NN + 1];
__device__ int    d_cursor[NN];
__device__ int    d_csrs[NE];        // src only (weights factored out)
__device__ u64    d_agg[64];
__device__ int    d_is64;
__device__ int    d_gstart[NG + 1];
__device__ float  d_mlpo[NG * 64];

__device__ __forceinline__ uint2 pack4h(float4 v) {
    __half2 a = __floats2half2_rn(v.x, v.y);
    __half2 b = __floats2half2_rn(v.z, v.w);
    uint2 r;
    r.x = *(unsigned*)&a;
    r.y = *(unsigned*)&b;
    return r;
}
__device__ __forceinline__ float4 unpack4h(uint2 u) {
    __half2 a = *(__half2*)&u.x;
    __half2 b = *(__half2*)&u.y;
    float2 f0 = __half22float2(a);
    float2 f1 = __half22float2(b);
    return make_float4(f0.x, f0.y, f1.x, f1.y);
}

__device__ __forceinline__ int ldidx(const void* p, long long i) {
    if (d_is64) return (int)((const long long*)p)[i];
    return ((const int*)p)[i];
}
// load 2 consecutive indices at even base
__device__ __forceinline__ void ldidx2(const void* p, long long base, int* o) {
    if (d_is64) {
        longlong2 a = __ldg((const longlong2*)p + (base >> 1));
        o[0] = (int)a.x; o[1] = (int)a.y;
    } else {
        int2 v = __ldg((const int2*)((const int*)p + base));
        o[0] = v.x; o[1] = v.y;
    }
}

// ---------------- prep ----------------
__global__ void k_init(const void* edge) {
    int i = blockIdx.x * blockDim.x + threadIdx.x;
    if (i == 0) {
        const int* p = (const int*)edge;
        int any = 0;
        for (int j = 0; j < 64; j++) any |= p[2 * j + 1];
        d_is64 = (any == 0) ? 1 : 0;
    }
    int i4 = i * 4;
    if (i4 + 3 < NN) *(int4*)&d_cnt[i4] = make_int4(0, 0, 0, 0);
    else for (int q = i4; q < NN; q++) if (q >= i4 && q < i4 + 4) d_cnt[q] = 0;
    if (i < 64) d_agg[i] = 0ull;
}

// 2 edges per thread (400k threads: still > SM saturation, 2x MLP per thread)
__global__ void k_hist(const void* edge) {
    int e2 = (blockIdx.x * blockDim.x + threadIdx.x) * 2;
    if (e2 >= NE) return;
    int c[2];
    ldidx2(edge, (long long)NE + e2, c);
    atomicAdd(&d_cnt[c[0]], 1);
    atomicAdd(&d_cnt[c[1]], 1);
}

// single-pass scan (aggregate lookback) + dinv + cursor
__global__ void k_scan() {
    __shared__ int sm[2][SCAN_BLK];
    __shared__ int pb[64];
    int t = threadIdx.x;
    int bid = blockIdx.x;
    int idx = bid * SCAN_BLK + t;
    int v = (idx < NN) ? d_cnt[idx] : 0;
    sm[0][t] = v;
    __syncthreads();
    int cur = 0;
    for (int d = 1; d < SCAN_BLK; d <<= 1) {
        int add = (t >= d) ? sm[cur][t - d] : 0;
        sm[cur ^ 1][t] = sm[cur][t] + add;
        cur ^= 1;
        __syncthreads();
    }
    int incl = sm[cur][t];
    if (t == SCAN_BLK - 1)
        atomicExch(&d_agg[bid], (1ull << 32) | (unsigned)incl);
    if (t < 64) {
        int val = 0;
        if (t < bid) {
            u64 w;
            do { w = atomicAdd(&d_agg[t], 0ull); } while ((w >> 32) == 0ull);
            val = (int)(unsigned)w;
        }
        pb[t] = val;
    }
    __syncthreads();
    if (t < 32) pb[t] += pb[t + 32];
    __syncthreads();
    if (t < 16) pb[t] += pb[t + 16];
    __syncthreads();
    if (t < 8) pb[t] += pb[t + 8];
    __syncthreads();
    if (t < 4) pb[t] += pb[t + 4];
    __syncthreads();
    int base = pb[0] + pb[1] + pb[2] + pb[3];
    int excl = base + incl - v;
    if (idx <= NN) d_off[idx] = excl;
    if (idx < NN) {
        d_dinv[idx] = rsqrtf((float)v + 1.0f);
        d_cursor[idx] = excl;
    }
}

// CSR fill: 2 edges per thread
__global__ void k_fill(const void* edge) {
    int e2 = (blockIdx.x * blockDim.x + threadIdx.x) * 2;
    if (e2 >= NE) return;
    int r[2], c[2];
    ldidx2(edge, e2, r);
    ldidx2(edge, (long long)NE + e2, c);
    int p0 = atomicAdd(&d_cursor[c[0]], 1);
    int p1 = atomicAdd(&d_cursor[c[1]], 1);
    d_csrs[p0] = r[0];
    d_csrs[p1] = r[1];
}

__global__ void k_wconv(const float* __restrict__ W) {
    int i = blockIdx.x * blockDim.x + threadIdx.x;
    if (i < 3 * NF * NF) d_Wh[i] = __float2half(W[i]);
}

__global__ void k_bounds(const void* batch) {
    int i = blockIdx.x * blockDim.x + threadIdx.x;
    if (i >= NN) return;
    int b = ldidx(batch, i);
    int prev = (i == 0) ? -1 : ldidx(batch, i - 1);
    for (int g = prev + 1; g <= b; g++) d_gstart[g] = i;
    if (i == NN - 1) {
        for (int g = b + 1; g <= NG; g++) d_gstart[g] = NN;
    }
}

#define SM_STRIDE 136   // halves; conflict-free mma fragment loads

// ---------------- HMMA core; epilogue scales row n by dinv[n] ----------------
__device__ __forceinline__ void mma_phase(const __half* Asm, const __half* Bsm,
                                          __half* C, int row0, int nrows, int tid)
{
    int lane = tid & 31, wid = tid >> 5;
    int wm = (wid & 3) * 32;
    int wn = (wid >> 2) * 64;
    int r = lane >> 2;
    int c2 = (lane & 3) * 2;

    float acc[2][8][4];
#pragma unroll
    for (int mt = 0; mt < 2; mt++)
#pragma unroll
        for (int nt = 0; nt < 8; nt++)
#pragma unroll
            for (int q = 0; q < 4; q++) acc[mt][nt][q] = 0.f;

#pragma unroll
    for (int ks = 0; ks < 8; ks++) {
        int kb = ks * 16;
        unsigned af[2][4];
#pragma unroll
        for (int mt = 0; mt < 2; mt++) {
            int rowb = wm + mt * 16;
            af[mt][0] = *(unsigned*)&Asm[(rowb + r) * SM_STRIDE + kb + c2];
            af[mt][1] = *(unsigned*)&Asm[(rowb + r + 8) * SM_STRIDE + kb + c2];
            af[mt][2] = *(unsigned*)&Asm[(rowb + r) * SM_STRIDE + kb + c2 + 8];
            af[mt][3] = *(unsigned*)&Asm[(rowb + r + 8) * SM_STRIDE + kb + c2 + 8];
        }
        unsigned bf[8][2];
#pragma unroll
        for (int nt = 0; nt < 8; nt++) {
            int n = wn + nt * 8 + r;
            bf[nt][0] = *(unsigned*)&Bsm[n * SM_STRIDE + kb + c2];
            bf[nt][1] = *(unsigned*)&Bsm[n * SM_STRIDE + kb + c2 + 8];
        }
#pragma unroll
        for (int mt = 0; mt < 2; mt++)
#pragma unroll
            for (int nt = 0; nt < 8; nt++) {
                asm volatile(
                    "mma.sync.aligned.m16n8k16.row.col.f32.f16.f16.f32 "
                    "{%0,%1,%2,%3}, {%4,%5,%6,%7}, {%8,%9}, {%0,%1,%2,%3};"
                    : "+f"(acc[mt][nt][0]), "+f"(acc[mt][nt][1]),
                      "+f"(acc[mt][nt][2]), "+f"(acc[mt][nt][3])
                    : "r"(af[mt][0]), "r"(af[mt][1]), "r"(af[mt][2]), "r"(af[mt][3]),
                      "r"(bf[nt][0]), "r"(bf[nt][1]));
            }
    }

#pragma unroll
    for (int mt = 0; mt < 2; mt++) {
        int gr0 = row0 + wm + mt * 16 + r;
        int gr1 = gr0 + 8;
        float dv0 = (gr0 < nrows) ? d_dinv[gr0] : 0.f;
        float dv1 = (gr1 < nrows) ? d_dinv[gr1] : 0.f;
#pragma unroll
        for (int nt = 0; nt < 8; nt++) {
            int gc = wn + nt * 8 + c2;
            __half2 h0 = __floats2half2_rn(dv0 * acc[mt][nt][0], dv0 * acc[mt][nt][1]);
            __half2 h1 = __floats2half2_rn(dv1 * acc[mt][nt][2], dv1 * acc[mt][nt][3]);
            if (gr0 < nrows) *(__half2*)(C + (size_t)gr0 * 128 + gc) = h0;
            if (gr1 < nrows) *(__half2*)(C + (size_t)gr1 * 128 + gc) = h1;
        }
    }
}

// GEMM: A fp32 (layer 1) or fp16 (layers 2,3); W fp16; C = dinv-scaled fp16
__global__ __launch_bounds__(256) void k_gemmT(
    const void* __restrict__ Ap, int a_fp32,
    const __half* __restrict__ Wh,
    __half* __restrict__ C, int nrows)
{
    extern __shared__ __half smh[];
    __half* Asm = smh;
    __half* Bsm = smh + 128 * SM_STRIDE;
    int tid = threadIdx.x;
    int row0 = blockIdx.x * 128;

    if (a_fp32) {
        const float* Af = (const float*)Ap;
#pragma unroll
        for (int i = 0; i < 16; i++) {
            int idx = tid + i * 256;
            int row = idx >> 5;
            int c4 = (idx & 31) << 2;
            float4 v = make_float4(0.f, 0.f, 0.f, 0.f);
            if (row0 + row < nrows)
                v = *(const float4*)(Af + (size_t)(row0 + row) * 128 + c4);
            *(uint2*)&Asm[row * SM_STRIDE + c4] = pack4h(v);
        }
    } else {
        const uint4* Ah = (const uint4*)Ap;
#pragma unroll
        for (int i = 0; i < 8; i++) {
            int idx = tid + i * 256;
            int row = idx >> 4;
            int c8 = (idx & 15) << 3;
            uint4 v = make_uint4(0u, 0u, 0u, 0u);
            if (row0 + row < nrows)
                v = Ah[(size_t)(row0 + row) * 16 + (idx & 15)];
            *(uint4*)&Asm[row * SM_STRIDE + c8] = v;
        }
    }
    {
        const uint4* Wv = (const uint4*)Wh;
#pragma unroll
        for (int i = 0; i < 8; i++) {
            int idx = tid + i * 256;
            int row = idx >> 4;
            int c8 = (idx & 15) << 3;
            *(uint4*)&Bsm[row * SM_STRIDE + c8] = Wv[idx];
        }
    }
    __syncthreads();
    mma_phase(Asm, Bsm, C, row0, nrows, tid);
}

// ---------------- agg: pure neighbor sum, L2-only gathers ----------------
__global__ __launch_bounds__(256) void k_agg(const __half* __restrict__ ht,
                                             const float* __restrict__ bias,
                                             __half* __restrict__ out)
{
    int node = (int)((blockIdx.x * (unsigned)blockDim.x + threadIdx.x) >> 5);
    if (node >= NN) return;
    int lane = threadIdx.x & 31;
    const uint2* base = (const uint2*)ht;

    float4 a0 = unpack4h(__ldcg(base + (size_t)node * 32 + lane));  // self term
    float4 a1 = make_float4(0.f, 0.f, 0.f, 0.f);
    float4 a2 = a1, a3 = a1;

    int p = d_off[node], e = d_off[node + 1];
    for (; p + 8 <= e; p += 8) {
        int ss[8];
        uint2 vv[8];
#pragma unroll
        for (int q = 0; q < 8; q++) ss[q] = __ldg(&d_csrs[p + q]);
#pragma unroll
        for (int q = 0; q < 8; q++) vv[q] = __ldcg(base + (size_t)ss[q] * 32 + lane);
#pragma unroll
        for (int q = 0; q < 8; q++) {
            float4 v = unpack4h(vv[q]);
            float4* a = (q & 3) == 0 ? &a0 : (q & 3) == 1 ? &a1 : (q & 3) == 2 ? &a2 : &a3;
            a->x += v.x; a->y += v.y; a->z += v.z; a->w += v.w;
        }
    }
    for (; p < e; p++) {
        int s = __ldg(&d_csrs[p]);
        float4 v = unpack4h(__ldcg(base + (size_t)s * 32 + lane));
        a0.x += v.x; a0.y += v.y; a0.z += v.z; a0.w += v.w;
    }
    float dv = d_dinv[node];
    float4 b4 = __ldg((const float4*)bias + lane);
    float4 rv;
    rv.x = fmaxf(fmaf(dv, a0.x + a1.x + a2.x + a3.x, b4.x), 0.f);
    rv.y = fmaxf(fmaf(dv, a0.y + a1.y + a2.y + a3.y, b4.y), 0.f);
    rv.z = fmaxf(fmaf(dv, a0.z + a1.z + a2.z + a3.z, b4.z), 0.f);
    rv.w = fmaxf(fmaf(dv, a0.w + a1.w + a2.w + a3.w, b4.w), 0.f);
    *(uint2*)(out + (size_t)node * 128 + lane * 4) = pack4h(rv);
}

// ---------------- small dense helpers ----------------
__device__ __forceinline__ float dotN(const float* __restrict__ a,
                                      const float* __restrict__ w, int n) {
    float s0 = 0.f, s1 = 0.f, s2 = 0.f, s3 = 0.f;
    for (int k = 0; k < n; k += 4) {
        float4 wv = __ldg((const float4*)(w + k));
        s0 = fmaf(a[k + 0], wv.x, s0);
        s1 = fmaf(a[k + 1], wv.y, s1);
        s2 = fmaf(a[k + 2], wv.z, s2);
        s3 = fmaf(a[k + 3], wv.w, s3);
    }
    return (s0 + s1) + (s2 + s3);
}

__global__ __launch_bounds__(256) void k_mlp(
    const float* __restrict__ mol,
    const float* __restrict__ mW, const float* __restrict__ mB,
    const float* __restrict__ moW, const float* __restrict__ moB)
{
    __shared__ float a[256], b[256];
    int g = blockIdx.x, t = threadIdx.x;
    a[t] = mol[g * 256 + t];
    __syncthreads();
    b[t] = fmaxf(dotN(a, mW + t * 256, 256) + mB[t], 0.f);
    __syncthreads();
    a[t] = fmaxf(dotN(b, mW + 65536 + t * 256, 256) + mB[256 + t], 0.f);
    __syncthreads();
    if (t < 64) d_mlpo[g * 64 + t] = fmaxf(dotN(a, moW + t * 256, 256) + moB[t], 0.f);
}

__global__ __launch_bounds__(256) void k_heads2(
    const __half* __restrict__ hnode,
    const float* __restrict__ goW, const float* __restrict__ goB,
    const float* __restrict__ p1W, const float* __restrict__ p1B,
    const float* __restrict__ p2W, const float* __restrict__ p2B,
    const float* __restrict__ oW, const float* __restrict__ oB,
    float* __restrict__ out)
{
    __shared__ float cat[192], pooled[128], red[256], b[256], a[256];
    int g = blockIdx.x, t = threadIdx.x;

    int s = d_gstart[g], e = d_gstart[g + 1];
    int f = t & 127, half = t >> 7;
    float c0 = 0.f, c1 = 0.f, c2 = 0.f, c3 = 0.f;
    int n = s + half;
    for (; n + 6 < e; n += 8) {
        c0 += __half2float(hnode[(size_t)n * 128 + f]);
        c1 += __half2float(hnode[(size_t)(n + 2) * 128 + f]);
        c2 += __half2float(hnode[(size_t)(n + 4) * 128 + f]);
        c3 += __half2float(hnode[(size_t)(n + 6) * 128 + f]);
    }
    for (; n < e; n += 2)
        c0 += __half2float(hnode[(size_t)n * 128 + f]);
    red[t] = (c0 + c1) + (c2 + c3);
    if (t < 64) cat[128 + t] = d_mlpo[g * 64 + t];
    __syncthreads();
    if (t < 128) pooled[t] = (red[t] + red[t + 128]) / (float)max(e - s, 1);
    __syncthreads();
    if (t < 128) cat[t] = dotN(pooled, goW + t * 128, 128) + goB[t];
    __syncthreads();

    b[t] = fmaxf(dotN(cat, p1W + t * 192, 192) + p1B[t], 0.f);
    __syncthreads();
    a[t] = fmaxf(dotN(b, p2W + t * 256, 256) + p2B[t], 0.f);
    __syncthreads();
    red[t] = a[t] * oW[t];
    __syncthreads();
    for (int d = 128; d > 0; d >>= 1) {
        if (t < d) red[t] += red[t + d];
        __syncthreads();
    }
    if (t == 0) out[g] = red[0] + oB[0];
}

// ---------------- host ----------------
#define GEMM_SMEM (2 * 128 * SM_STRIDE * (int)sizeof(__half))

struct HxCtx {
    cudaStream_t s1, s2;
    cudaEvent_t ev0, ev1, ev2, ev3, ev4;
    HxCtx() {
        cudaStreamCreateWithFlags(&s1, cudaStreamNonBlocking);
        cudaStreamCreateWithFlags(&s2, cudaStreamNonBlocking);
        cudaEvent_t* evs[5] = {&ev0, &ev1, &ev2, &ev3, &ev4};
        for (int i = 0; i < 5; i++)
            cudaEventCreateWithFlags(evs[i], cudaEventDisableTiming);
        cudaFuncSetAttribute(k_gemmT, cudaFuncAttributeMaxDynamicSharedMemorySize, GEMM_SMEM);
    }
};

extern "C" void kernel_launch(void* const* d_in, const int* in_sizes, int n_in,
                              void* d_out, int out_size)
{
    static HxCtx ctx;

    const float* x    = (const float*)d_in[0];
    const void*  ei   = d_in[1];
    const void*  bi   = d_in[2];
    const float* mol  = (const float*)d_in[3];
    const float* gcnW = (const float*)d_in[4];
    const float* gcnB = (const float*)d_in[5];
    const float* goW  = (const float*)d_in[6];
    const float* goB  = (const float*)d_in[7];
    const float* mW   = (const float*)d_in[8];
    const float* mB   = (const float*)d_in[9];
    const float* moW  = (const float*)d_in[10];
    const float* moB  = (const float*)d_in[11];
    const float* p1W  = (const float*)d_in[12];
    const float* p1B  = (const float*)d_in[13];
    const float* p2W  = (const float*)d_in[14];
    const float* p2B  = (const float*)d_in[15];
    const float* oW   = (const float*)d_in[16];
    const float* oB   = (const float*)d_in[17];
    float* out = (float*)d_out;

    void *pT, *pX, *pW;
    cudaGetSymbolAddress(&pT, d_hT);
    cudaGetSymbolAddress(&pX, d_hX);
    cudaGetSymbolAddress(&pW, d_Wh);
    __half* hT = (__half*)pT;
    __half* hX = (__half*)pX;
    __half* Wh = (__half*)pW;

    const int nthr = 256;
    int gN = (NN + nthr - 1) / nthr;
    int gI = (NN / 4 + nthr - 1) / nthr;
    int gE2 = (NE / 2 + nthr - 1) / nthr;
    int gGemm = (NN + 127) / 128;
    int gAgg = (NN * 32 + nthr - 1) / nthr;

    cudaStream_t L = 0;

    // init (+is64 detect, scan flag reset)
    k_init<<<gI, nthr, 0, L>>>(ei);
    cudaEventRecord(ctx.ev0, L);
    cudaStreamWaitEvent(ctx.s1, ctx.ev0, 0);
    cudaStreamWaitEvent(ctx.s2, ctx.ev0, 0);

    // s1: CSR prep (2 edges/thread — still >SM saturation)
    k_hist<<<gE2, nthr, 0, ctx.s1>>>(ei);
    k_scan<<<SCAN_NBLK, SCAN_BLK, 0, ctx.s1>>>();
    cudaEventRecord(ctx.ev4, ctx.s1);            // dinv ready
    k_fill<<<gE2, nthr, 0, ctx.s1>>>(ei);
    cudaEventRecord(ctx.ev1, ctx.s1);            // CSR ready

    // s2: wconv, bounds, mlp
    k_wconv<<<(3 * NF * NF + 255) / 256, 256, 0, ctx.s2>>>(gcnW);
    cudaEventRecord(ctx.ev3, ctx.s2);
    k_bounds<<<gN, nthr, 0, ctx.s2>>>(bi);
    k_mlp<<<NG, nthr, 0, ctx.s2>>>(mol, mW, mB, moW, moB);
    cudaEventRecord(ctx.ev2, ctx.s2);

    // L: GCN stack (GEMM1 needs dinv for epilogue scaling + Wh)
    cudaStreamWaitEvent(L, ctx.ev3, 0);
    cudaStreamWaitEvent(L, ctx.ev4, 0);
    k_gemmT<<<gGemm, 256, GEMM_SMEM, L>>>(x, 1, Wh, hT, NN);
    cudaStreamWaitEvent(L, ctx.ev1, 0);
    k_agg<<<gAgg, 256, 0, L>>>(hT, gcnB, hX);
    k_gemmT<<<gGemm, 256, GEMM_SMEM, L>>>(hX, 0, Wh + NF * NF, hT, NN);
    k_agg<<<gAgg, 256, 0, L>>>(hT, gcnB + 128, hX);
    k_gemmT<<<gGemm, 256, GEMM_SMEM, L>>>(hX, 0, Wh + 2 * NF * NF, hT, NN);
    k_agg<<<gAgg, 256, 0, L>>>(hT, gcnB + 256, hX);

    cudaStreamWaitEvent(L, ctx.ev2, 0);
    k_heads2<<<NG, 256, 0, L>>>(hX, goW, goB, p1W, p1B, p2W, p2B, oW, oB, out);
}

// round 12
// speedup vs baseline: 1.1411x; 1.0886x over previous
#include <cuda_runtime.h>
#include <cuda_fp16.h>

#define NN 50000
#define NE 800000
#define NG 256
#define NF 128
#define SCAN_BLK 1024
#define SCAN_NBLK 49   // 49*1024 = 50176 >= NN+1

typedef unsigned long long u64;

// ---------------- device scratch (no allocation allowed) ----------------
__device__ __align__(16) __half d_hT[NN * NF];     // dinv-scaled GEMM out
__device__ __align__(16) __half d_hX[NN * NF];     // agg out
__device__ __align__(16) __half d_Wh[3 * NF * NF];
__device__ float  d_dinv[NN];
__device__ int    d_cnt[NN];
__device__ int    d_off[NN + 1];
__device__ int    d_cursor[NN];
__device__ int    d_csrs[NE];        // src only (weights factored out)
__device__ u64    d_agg[64];
__device__ int    d_is64;
__device__ int    d_gstart[NG + 1];
__device__ float  d_mlpo[NG * 64];

__device__ __forceinline__ uint2 pack4h(float4 v) {
    __half2 a = __floats2half2_rn(v.x, v.y);
    __half2 b = __floats2half2_rn(v.z, v.w);
    uint2 r;
    r.x = *(unsigned*)&a;
    r.y = *(unsigned*)&b;
    return r;
}
__device__ __forceinline__ float4 unpack4h(uint2 u) {
    __half2 a = *(__half2*)&u.x;
    __half2 b = *(__half2*)&u.y;
    float2 f0 = __half22float2(a);
    float2 f1 = __half22float2(b);
    return make_float4(f0.x, f0.y, f1.x, f1.y);
}
__device__ __forceinline__ void add8(float* a, uint4 v) {
    __half2* hv = (__half2*)&v;
#pragma unroll
    for (int j = 0; j < 4; j++) {
        float2 f = __half22float2(hv[j]);
        a[2 * j] += f.x;
        a[2 * j + 1] += f.y;
    }
}

__device__ __forceinline__ int ldidx(const void* p, long long i) {
    if (d_is64) return (int)((const long long*)p)[i];
    return ((const int*)p)[i];
}

// ---------------- prep ----------------
__global__ void k_init(const void* edge) {
    int i = blockIdx.x * blockDim.x + threadIdx.x;
    if (i == 0) {
        const int* p = (const int*)edge;
        int any = 0;
        for (int j = 0; j < 64; j++) any |= p[2 * j + 1];
        d_is64 = (any == 0) ? 1 : 0;
    }
    if (i < NN) d_cnt[i] = 0;
    if (i < 64) d_agg[i] = 0ull;
}

__global__ void k_hist(const void* edge) {
    int e = blockIdx.x * blockDim.x + threadIdx.x;
    if (e >= NE) return;
    int c = ldidx(edge, (long long)NE + e);
    atomicAdd(&d_cnt[c], 1);
}

// single-pass scan (aggregate lookback) + dinv + cursor
__global__ void k_scan() {
    __shared__ int sm[2][SCAN_BLK];
    __shared__ int pb[64];
    int t = threadIdx.x;
    int bid = blockIdx.x;
    int idx = bid * SCAN_BLK + t;
    int v = (idx < NN) ? d_cnt[idx] : 0;
    sm[0][t] = v;
    __syncthreads();
    int cur = 0;
    for (int d = 1; d < SCAN_BLK; d <<= 1) {
        int add = (t >= d) ? sm[cur][t - d] : 0;
        sm[cur ^ 1][t] = sm[cur][t] + add;
        cur ^= 1;
        __syncthreads();
    }
    int incl = sm[cur][t];
    if (t == SCAN_BLK - 1)
        atomicExch(&d_agg[bid], (1ull << 32) | (unsigned)incl);
    if (t < 64) {
        int val = 0;
        if (t < bid) {
            u64 w;
            do { w = atomicAdd(&d_agg[t], 0ull); } while ((w >> 32) == 0ull);
            val = (int)(unsigned)w;
        }
        pb[t] = val;
    }
    __syncthreads();
    if (t < 32) pb[t] += pb[t + 32];
    __syncthreads();
    if (t < 16) pb[t] += pb[t + 16];
    __syncthreads();
    if (t < 8) pb[t] += pb[t + 8];
    __syncthreads();
    if (t < 4) pb[t] += pb[t + 4];
    __syncthreads();
    int base = pb[0] + pb[1] + pb[2] + pb[3];
    int excl = base + incl - v;
    if (idx <= NN) d_off[idx] = excl;
    if (idx < NN) {
        d_dinv[idx] = rsqrtf((float)v + 1.0f);
        d_cursor[idx] = excl;
    }
}

// CSR fill: 1 edge/thread (max resident threads = max atomic throughput)
__global__ void k_fill(const void* edge) {
    int e = blockIdx.x * blockDim.x + threadIdx.x;
    if (e >= NE) return;
    int r = ldidx(edge, e);
    int c = ldidx(edge, (long long)NE + e);
    int p = atomicAdd(&d_cursor[c], 1);
    d_csrs[p] = r;
}

__global__ void k_wconv(const float* __restrict__ W) {
    int i = blockIdx.x * blockDim.x + threadIdx.x;
    if (i < 3 * NF * NF) d_Wh[i] = __float2half(W[i]);
}

__global__ void k_bounds(const void* batch) {
    int i = blockIdx.x * blockDim.x + threadIdx.x;
    if (i >= NN) return;
    int b = ldidx(batch, i);
    int prev = (i == 0) ? -1 : ldidx(batch, i - 1);
    for (int g = prev + 1; g <= b; g++) d_gstart[g] = i;
    if (i == NN - 1) {
        for (int g = b + 1; g <= NG; g++) d_gstart[g] = NN;
    }
}

#define SM_STRIDE 136   // halves; conflict-free mma fragment loads

// ---------------- HMMA core; epilogue scales row n by dinv[n] ----------------
__device__ __forceinline__ void mma_phase(const __half* Asm, const __half* Bsm,
                                          __half* C, int row0, int nrows, int tid)
{
    int lane = tid & 31, wid = tid >> 5;
    int wm = (wid & 3) * 32;
    int wn = (wid >> 2) * 64;
    int r = lane >> 2;
    int c2 = (lane & 3) * 2;

    float acc[2][8][4];
#pragma unroll
    for (int mt = 0; mt < 2; mt++)
#pragma unroll
        for (int nt = 0; nt < 8; nt++)
#pragma unroll
            for (int q = 0; q < 4; q++) acc[mt][nt][q] = 0.f;

#pragma unroll
    for (int ks = 0; ks < 8; ks++) {
        int kb = ks * 16;
        unsigned af[2][4];
#pragma unroll
        for (int mt = 0; mt < 2; mt++) {
            int rowb = wm + mt * 16;
            af[mt][0] = *(unsigned*)&Asm[(rowb + r) * SM_STRIDE + kb + c2];
            af[mt][1] = *(unsigned*)&Asm[(rowb + r + 8) * SM_STRIDE + kb + c2];
            af[mt][2] = *(unsigned*)&Asm[(rowb + r) * SM_STRIDE + kb + c2 + 8];
            af[mt][3] = *(unsigned*)&Asm[(rowb + r + 8) * SM_STRIDE + kb + c2 + 8];
        }
        unsigned bf[8][2];
#pragma unroll
        for (int nt = 0; nt < 8; nt++) {
            int n = wn + nt * 8 + r;
            bf[nt][0] = *(unsigned*)&Bsm[n * SM_STRIDE + kb + c2];
            bf[nt][1] = *(unsigned*)&Bsm[n * SM_STRIDE + kb + c2 + 8];
        }
#pragma unroll
        for (int mt = 0; mt < 2; mt++)
#pragma unroll
            for (int nt = 0; nt < 8; nt++) {
                asm volatile(
                    "mma.sync.aligned.m16n8k16.row.col.f32.f16.f16.f32 "
                    "{%0,%1,%2,%3}, {%4,%5,%6,%7}, {%8,%9}, {%0,%1,%2,%3};"
                    : "+f"(acc[mt][nt][0]), "+f"(acc[mt][nt][1]),
                      "+f"(acc[mt][nt][2]), "+f"(acc[mt][nt][3])
                    : "r"(af[mt][0]), "r"(af[mt][1]), "r"(af[mt][2]), "r"(af[mt][3]),
                      "r"(bf[nt][0]), "r"(bf[nt][1]));
            }
    }

#pragma unroll
    for (int mt = 0; mt < 2; mt++) {
        int gr0 = row0 + wm + mt * 16 + r;
        int gr1 = gr0 + 8;
        float dv0 = (gr0 < nrows) ? d_dinv[gr0] : 0.f;
        float dv1 = (gr1 < nrows) ? d_dinv[gr1] : 0.f;
#pragma unroll
        for (int nt = 0; nt < 8; nt++) {
            int gc = wn + nt * 8 + c2;
            __half2 h0 = __floats2half2_rn(dv0 * acc[mt][nt][0], dv0 * acc[mt][nt][1]);
            __half2 h1 = __floats2half2_rn(dv1 * acc[mt][nt][2], dv1 * acc[mt][nt][3]);
            if (gr0 < nrows) *(__half2*)(C + (size_t)gr0 * 128 + gc) = h0;
            if (gr1 < nrows) *(__half2*)(C + (size_t)gr1 * 128 + gc) = h1;
        }
    }
}

// GEMM: A fp32 (layer 1) or fp16 (layers 2,3); W fp16; C = dinv-scaled fp16
__global__ __launch_bounds__(256) void k_gemmT(
    const void* __restrict__ Ap, int a_fp32,
    const __half* __restrict__ Wh,
    __half* __restrict__ C, int nrows)
{
    extern __shared__ __half smh[];
    __half* Asm = smh;
    __half* Bsm = smh + 128 * SM_STRIDE;
    int tid = threadIdx.x;
    int row0 = blockIdx.x * 128;

    if (a_fp32) {
        const float* Af = (const float*)Ap;
#pragma unroll
        for (int i = 0; i < 16; i++) {
            int idx = tid + i * 256;
            int row = idx >> 5;
            int c4 = (idx & 31) << 2;
            float4 v = make_float4(0.f, 0.f, 0.f, 0.f);
            if (row0 + row < nrows)
                v = *(const float4*)(Af + (size_t)(row0 + row) * 128 + c4);
            *(uint2*)&Asm[row * SM_STRIDE + c4] = pack4h(v);
        }
    } else {
        const uint4* Ah = (const uint4*)Ap;
#pragma unroll
        for (int i = 0; i < 8; i++) {
            int idx = tid + i * 256;
            int row = idx >> 4;
            int c8 = (idx & 15) << 3;
            uint4 v = make_uint4(0u, 0u, 0u, 0u);
            if (row0 + row < nrows)
                v = Ah[(size_t)(row0 + row) * 16 + (idx & 15)];
            *(uint4*)&Asm[row * SM_STRIDE + c8] = v;
        }
    }
    {
        const uint4* Wv = (const uint4*)Wh;
#pragma unroll
        for (int i = 0; i < 8; i++) {
            int idx = tid + i * 256;
            int row = idx >> 4;
            int c8 = (idx & 15) << 3;
            *(uint4*)&Bsm[row * SM_STRIDE + c8] = Wv[idx];
        }
    }
    __syncthreads();
    mma_phase(Asm, Bsm, C, row0, nrows, tid);
}

// ---------------- agg v2: warp per node, LDG.128 lanes, even/odd half-warps ----------------
// Lanes 0-15 sum even neighbors, lanes 16-31 odd neighbors; each lane covers
// 8 features (one uint4 of the 256B row). Halves combined via shfl at the end.
__global__ __launch_bounds__(256) void k_agg(const __half* __restrict__ ht,
                                             const float* __restrict__ bias,
                                             __half* __restrict__ out)
{
    int node = (int)((blockIdx.x * (unsigned)blockDim.x + threadIdx.x) >> 5);
    if (node >= NN) return;
    int lane = threadIdx.x & 31;
    int half = lane >> 4;      // 0: even neighbors, 1: odd neighbors
    int li = lane & 15;        // uint4 index within row
    const uint4* base = (const uint4*)ht;   // 16 uint4 per 128-half row

    float a[8];
#pragma unroll
    for (int j = 0; j < 8; j++) a[j] = 0.f;

    // self term (half 0 only)
    if (half == 0) add8(a, __ldg(base + (size_t)node * 16 + li));

    int p = d_off[node], e = d_off[node + 1];
    // 16 neighbors per iteration: 8 per half-warp
    for (; p + 16 <= e; p += 16) {
        int ss[8];
        uint4 vv[8];
#pragma unroll
        for (int k = 0; k < 8; k++) ss[k] = __ldg(&d_csrs[p + 2 * k + half]);
#pragma unroll
        for (int k = 0; k < 8; k++) vv[k] = __ldg(base + (size_t)ss[k] * 16 + li);
#pragma unroll
        for (int k = 0; k < 8; k++) add8(a, vv[k]);
    }
    // neighbor pairs
    for (; p + 2 <= e; p += 2) {
        int s = __ldg(&d_csrs[p + half]);
        add8(a, __ldg(base + (size_t)s * 16 + li));
    }
    // odd tail (half 0 only)
    if (p < e && half == 0) {
        int s = __ldg(&d_csrs[p]);
        add8(a, __ldg(base + (size_t)s * 16 + li));
    }

    // combine even/odd halves
#pragma unroll
    for (int j = 0; j < 8; j++)
        a[j] += __shfl_down_sync(0xffffffffu, a[j], 16);

    if (half == 0) {
        float dv = d_dinv[node];
        float4 b0 = __ldg((const float4*)bias + li * 2);
        float4 b1 = __ldg((const float4*)bias + li * 2 + 1);
        __half2 h[4];
        h[0] = __floats2half2_rn(fmaxf(fmaf(dv, a[0], b0.x), 0.f),
                                 fmaxf(fmaf(dv, a[1], b0.y), 0.f));
        h[1] = __floats2half2_rn(fmaxf(fmaf(dv, a[2], b0.z), 0.f),
                                 fmaxf(fmaf(dv, a[3], b0.w), 0.f));
        h[2] = __floats2half2_rn(fmaxf(fmaf(dv, a[4], b1.x), 0.f),
                                 fmaxf(fmaf(dv, a[5], b1.y), 0.f));
        h[3] = __floats2half2_rn(fmaxf(fmaf(dv, a[6], b1.z), 0.f),
                                 fmaxf(fmaf(dv, a[7], b1.w), 0.f));
        *(uint4*)(out + (size_t)node * 128 + li * 8) = *(uint4*)h;
    }
}

// ---------------- small dense helpers ----------------
__device__ __forceinline__ float dotN(const float* __restrict__ a,
                                      const float* __restrict__ w, int n) {
    float s0 = 0.f, s1 = 0.f, s2 = 0.f, s3 = 0.f;
    for (int k = 0; k < n; k += 4) {
        float4 wv = __ldg((const float4*)(w + k));
        s0 = fmaf(a[k + 0], wv.x, s0);
        s1 = fmaf(a[k + 1], wv.y, s1);
        s2 = fmaf(a[k + 2], wv.z, s2);
        s3 = fmaf(a[k + 3], wv.w, s3);
    }
    return (s0 + s1) + (s2 + s3);
}

__global__ __launch_bounds__(256) void k_mlp(
    const float* __restrict__ mol,
    const float* __restrict__ mW, const float* __restrict__ mB,
    const float* __restrict__ moW, const float* __restrict__ moB)
{
    __shared__ float a[256], b[256];
    int g = blockIdx.x, t = threadIdx.x;
    a[t] = mol[g * 256 + t];
    __syncthreads();
    b[t] = fmaxf(dotN(a, mW + t * 256, 256) + mB[t], 0.f);
    __syncthreads();
    a[t] = fmaxf(dotN(b, mW + 65536 + t * 256, 256) + mB[256 + t], 0.f);
    __syncthreads();
    if (t < 64) d_mlpo[g * 64 + t] = fmaxf(dotN(a, moW + t * 256, 256) + moB[t], 0.f);
}

__global__ __launch_bounds__(256) void k_heads2(
    const __half* __restrict__ hnode,
    const float* __restrict__ goW, const float* __restrict__ goB,
    const float* __restrict__ p1W, const float* __restrict__ p1B,
    const float* __restrict__ p2W, const float* __restrict__ p2B,
    const float* __restrict__ oW, const float* __restrict__ oB,
    float* __restrict__ out)
{
    __shared__ float cat[192], pooled[128], red[256], b[256], a[256];
    int g = blockIdx.x, t = threadIdx.x;

    int s = d_gstart[g], e = d_gstart[g + 1];
    int f = t & 127, half = t >> 7;
    float c0 = 0.f, c1 = 0.f, c2 = 0.f, c3 = 0.f;
    int n = s + half;
    for (; n + 6 < e; n += 8) {
        c0 += __half2float(hnode[(size_t)n * 128 + f]);
        c1 += __half2float(hnode[(size_t)(n + 2) * 128 + f]);
        c2 += __half2float(hnode[(size_t)(n + 4) * 128 + f]);
        c3 += __half2float(hnode[(size_t)(n + 6) * 128 + f]);
    }
    for (; n < e; n += 2)
        c0 += __half2float(hnode[(size_t)n * 128 + f]);
    red[t] = (c0 + c1) + (c2 + c3);
    if (t < 64) cat[128 + t] = d_mlpo[g * 64 + t];
    __syncthreads();
    if (t < 128) pooled[t] = (red[t] + red[t + 128]) / (float)max(e - s, 1);
    __syncthreads();
    if (t < 128) cat[t] = dotN(pooled, goW + t * 128, 128) + goB[t];
    __syncthreads();

    b[t] = fmaxf(dotN(cat, p1W + t * 192, 192) + p1B[t], 0.f);
    __syncthreads();
    a[t] = fmaxf(dotN(b, p2W + t * 256, 256) + p2B[t], 0.f);
    __syncthreads();
    red[t] = a[t] * oW[t];
    __syncthreads();
    for (int d = 128; d > 0; d >>= 1) {
        if (t < d) red[t] += red[t + d];
        __syncthreads();
    }
    if (t == 0) out[g] = red[0] + oB[0];
}

// ---------------- host ----------------
#define GEMM_SMEM (2 * 128 * SM_STRIDE * (int)sizeof(__half))

struct HxCtx {
    cudaStream_t s1, s2;
    cudaEvent_t ev0, ev1, ev2, ev3, ev4;
    HxCtx() {
        cudaStreamCreateWithFlags(&s1, cudaStreamNonBlocking);
        cudaStreamCreateWithFlags(&s2, cudaStreamNonBlocking);
        cudaEvent_t* evs[5] = {&ev0, &ev1, &ev2, &ev3, &ev4};
        for (int i = 0; i < 5; i++)
            cudaEventCreateWithFlags(evs[i], cudaEventDisableTiming);
        cudaFuncSetAttribute(k_gemmT, cudaFuncAttributeMaxDynamicSharedMemorySize, GEMM_SMEM);
    }
};

extern "C" void kernel_launch(void* const* d_in, const int* in_sizes, int n_in,
                              void* d_out, int out_size)
{
    static HxCtx ctx;

    const float* x    = (const float*)d_in[0];
    const void*  ei   = d_in[1];
    const void*  bi   = d_in[2];
    const float* mol  = (const float*)d_in[3];
    const float* gcnW = (const float*)d_in[4];
    const float* gcnB = (const float*)d_in[5];
    const float* goW  = (const float*)d_in[6];
    const float* goB  = (const float*)d_in[7];
    const float* mW   = (const float*)d_in[8];
    const float* mB   = (const float*)d_in[9];
    const float* moW  = (const float*)d_in[10];
    const float* moB  = (const float*)d_in[11];
    const float* p1W  = (const float*)d_in[12];
    const float* p1B  = (const float*)d_in[13];
    const float* p2W  = (const float*)d_in[14];
    const float* p2B  = (const float*)d_in[15];
    const float* oW   = (const float*)d_in[16];
    const float* oB   = (const float*)d_in[17];
    float* out = (float*)d_out;

    void *pT, *pX, *pW;
    cudaGetSymbolAddress(&pT, d_hT);
    cudaGetSymbolAddress(&pX, d_hX);
    cudaGetSymbolAddress(&pW, d_Wh);
    __half* hT = (__half*)pT;
    __half* hX = (__half*)pX;
    __half* Wh = (__half*)pW;

    const int nthr = 256;
    int gN = (NN + nthr - 1) / nthr;
    int gE = (NE + nthr - 1) / nthr;
    int gGemm = (NN + 127) / 128;
    int gAgg = (NN * 32 + nthr - 1) / nthr;

    cudaStream_t L = 0;

    // init (+is64 detect, scan flag reset)
    k_init<<<gN, nthr, 0, L>>>(ei);
    cudaEventRecord(ctx.ev0, L);
    cudaStreamWaitEvent(ctx.s1, ctx.ev0, 0);
    cudaStreamWaitEvent(ctx.s2, ctx.ev0, 0);

    // s1: CSR prep (scalar hist/fill — max resident threads)
    k_hist<<<gE, nthr, 0, ctx.s1>>>(ei);
    k_scan<<<SCAN_NBLK, SCAN_BLK, 0, ctx.s1>>>();
    cudaEventRecord(ctx.ev4, ctx.s1);            // dinv ready
    k_fill<<<gE, nthr, 0, ctx.s1>>>(ei);
    cudaEventRecord(ctx.ev1, ctx.s1);            // CSR ready

    // s2: wconv, bounds, mlp
    k_wconv<<<(3 * NF * NF + 255) / 256, 256, 0, ctx.s2>>>(gcnW);
    cudaEventRecord(ctx.ev3, ctx.s2);
    k_bounds<<<gN, nthr, 0, ctx.s2>>>(bi);
    k_mlp<<<NG, nthr, 0, ctx.s2>>>(mol, mW, mB, moW, moB);
    cudaEventRecord(ctx.ev2, ctx.s2);

    // L: GCN stack (GEMM1 needs dinv for epilogue scaling + Wh)
    cudaStreamWaitEvent(L, ctx.ev3, 0);
    cudaStreamWaitEvent(L, ctx.ev4, 0);
    k_gemmT<<<gGemm, 256, GEMM_SMEM, L>>>(x, 1, Wh, hT, NN);
    cudaStreamWaitEvent(L, ctx.ev1, 0);
    k_agg<<<gAgg, 256, 0, L>>>(hT, gcnB, hX);
    k_gemmT<<<gGemm, 256, GEMM_SMEM, L>>>(hX, 0, Wh + NF * NF, hT, NN);
    k_agg<<<gAgg, 256, 0, L>>>(hT, gcnB + 128, hX);
    k_gemmT<<<gGemm, 256, GEMM_SMEM, L>>>(hX, 0, Wh + 2 * NF * NF, hT, NN);
    k_agg<<<gAgg, 256, 0, L>>>(hT, gcnB + 256, hX);

    cudaStreamWaitEvent(L, ctx.ev2, 0);
    k_heads2<<<NG, 256, 0, L>>>(hX, goW, goB, p1W, p1B, p2W, p2B, oW, oB, out);
}